// round 16
// baseline (speedup 1.0000x reference)
#include <cuda_runtime.h>
#include <cuda_fp16.h>
#include <cstddef>

#define TT 4096
#define BB 256

// ---- scratch (static __device__, no allocation) ----
__device__ float2   g_E [(size_t)(TT + 1) * BB];   // emission probs softmax, +1 pad row
__device__ unsigned g_h [(size_t)BB * TT];         // GRU hidden (half2), [b][t]
__device__ float2   g_va[(size_t)BB * TT];         // forward linear alpha (arbitrary per-t scale), [b][t]
__device__ float2   g_vb[(size_t)BB * TT];         // backward linear beta  (arbitrary per-t scale), [b][t]

__device__ __forceinline__ float tanha(float x) {
    float r; asm("tanh.approx.f32 %0, %1;" : "=f"(r) : "f"(x)); return r;
}
__device__ __forceinline__ float frcp(float x) {
    float r; asm("rcp.approx.f32 %0, %1;" : "=f"(r) : "f"(x)); return r;
}
__device__ __forceinline__ unsigned h2bits(__half2 h) {
    return *reinterpret_cast<unsigned*>(&h);
}
__device__ __forceinline__ __half2 bits2h(unsigned u) {
    return *reinterpret_cast<__half2*>(&u);
}

// =====================================================================
// K1: emitter probabilities (tanh MLP D=3 -> 8 -> K=2, softmax)
// 128-thr block handles a 32b x 64t double tile. Cooperative float4
// loads (6+6 LDG.128/thread, all in flight before one barrier), scalar
// smem transpose, coalesced g_E stores.
// grid = (T/64) * (B/32) = 64 * 8 = 512
// =====================================================================
__global__ __launch_bounds__(128) void k1_emit(
    const float* __restrict__ x,
    const float* __restrict__ fc1w, const float* __restrict__ fc1b,
    const float* __restrict__ fc2w, const float* __restrict__ fc2b)
{
    __shared__ float xs[2][3][32][33];
    __shared__ float sp[50];
    int tid = threadIdx.x, lane = tid & 31, wid = tid >> 5;

    if (tid < 24)      sp[tid] = fc1w[tid];
    else if (tid < 32) sp[tid] = fc1b[tid - 24];
    else if (tid < 48) sp[tid] = fc2w[tid - 32];
    else if (tid < 50) sp[tid] = fc2b[tid - 48];

    int eb = blockIdx.x;
    int tb = eb & 63, bb = eb >> 6;
    int t0 = tb * 64, b0 = bb * 32;

    // pad row for backward E prefetch (block 0: 128 threads x 2 entries)
    if (eb == 0) {
        g_E[(size_t)TT * BB + tid]       = make_float2(1.f, 1.f);
        g_E[(size_t)TT * BB + 128 + tid] = make_float2(1.f, 1.f);
    }

    // ---- load phase: 2 tiles x 768 float4 / 128 thr = 6+6 per thread ----
    // row r's 32-t tile = 96 floats = 24 float4 (16B-aligned: t0*3 % 4 == 0)
    float4 v0[6], v1[6];
    int rows[6], fs[6];
#pragma unroll
    for (int j = 0; j < 6; j++) {
        int k = tid + 128 * j;
        rows[j] = k / 24; fs[j] = k % 24;
        const float4* p = (const float4*)(x + ((size_t)(b0 + rows[j]) * TT + t0) * 3) + fs[j];
        v0[j] = __ldg(p);
        v1[j] = __ldg(p + 24);              // +32 t = +96 floats = +24 float4
    }
#pragma unroll
    for (int j = 0; j < 6; j++) {
        float a0[4] = {v0[j].x, v0[j].y, v0[j].z, v0[j].w};
        float a1[4] = {v1[j].x, v1[j].y, v1[j].z, v1[j].w};
#pragma unroll
        for (int c = 0; c < 4; c++) {
            int w = fs[j] * 4 + c;
            int tl = w / 3, d = w - 3 * tl;
            xs[0][d][tl][rows[j]] = a0[c];
            xs[1][d][tl][rows[j]] = a1[c];
        }
    }
    __syncthreads();

    // ---- compute phase: warp wid handles t rows wid*8..wid*8+7 per tile ----
#pragma unroll
    for (int s = 0; s < 2; s++) {
#pragma unroll
        for (int k = 0; k < 8; k++) {
            int tl = wid * 8 + k;
            float x0 = xs[s][0][tl][lane];
            float x1 = xs[s][1][tl][lane];
            float x2 = xs[s][2][tl][lane];
            float l0 = sp[48], l1 = sp[49];
#pragma unroll
            for (int e = 0; e < 8; e++) {
                float hv = tanha(fmaf(sp[e * 3 + 0], x0,
                                 fmaf(sp[e * 3 + 1], x1,
                                 fmaf(sp[e * 3 + 2], x2, sp[24 + e]))));
                l0 = fmaf(sp[32 + e], hv, l0);
                l1 = fmaf(sp[40 + e], hv, l1);
            }
            float ed  = __expf(l1 - l0);
            float inv = frcp(1.f + ed);
            g_E[(size_t)(t0 + s * 32 + tl) * BB + b0 + lane] = make_float2(inv, ed * inv);
        }
    }
}

// =====================================================================
// K2 helpers: register-resident pipelined buffers (constant indices only)
// =====================================================================
struct GruW {
    float wr00, wr01, wr10, wr11;      // 0.5 * w_hh r-rows
    float wz00, wz01, wz10, wz11;      // 0.5 * w_hh z-rows
    float wn00, wn01, wn10, wn11;      // w_hh n-rows
    float bn0, bn1;                    // b_hh n-part
    float wi[6][3];                    // w_ih rows (r,z rows pre-halved)
    float bi[6];                       // r,z: 0.5*(b_ih+b_hh); n: b_ih
};

__device__ __forceinline__ void x_load(float4 (&X)[6], const float4* xp, int grp)
{
#pragma unroll
    for (int i = 0; i < 6; i++) X[i] = xp[grp * 6 + i];
}

// 8 GRU steps; input gates computed inline from x (off the tanh chain).
__device__ __forceinline__ void gru_body(const GruW& W, const float4 (&X)[6],
                                         float& h0, float& h1,
                                         unsigned* __restrict__ hout, int tb, bool store)
{
    float xs[24];
#pragma unroll
    for (int i = 0; i < 6; i++) {
        xs[i * 4 + 0] = X[i].x; xs[i * 4 + 1] = X[i].y;
        xs[i * 4 + 2] = X[i].z; xs[i * 4 + 3] = X[i].w;
    }
    unsigned hv[8];
#pragma unroll
    for (int u = 0; u < 8; u++) {
        float x0 = xs[u * 3 + 0], x1 = xs[u * 3 + 1], x2 = xs[u * 3 + 2];
        float ig[6];
#pragma unroll
        for (int j = 0; j < 6; j++)
            ig[j] = fmaf(W.wi[j][0], x0,
                    fmaf(W.wi[j][1], x1,
                    fmaf(W.wi[j][2], x2, W.bi[j])));
        float tr0 = tanha(fmaf(W.wr00, h0, fmaf(W.wr01, h1, ig[0])));
        float tr1 = tanha(fmaf(W.wr10, h0, fmaf(W.wr11, h1, ig[1])));
        float tz0 = tanha(fmaf(W.wz00, h0, fmaf(W.wz01, h1, ig[2])));
        float tz1 = tanha(fmaf(W.wz10, h0, fmaf(W.wz11, h1, ig[3])));
        float hn0 = fmaf(W.wn00, h0, fmaf(W.wn01, h1, W.bn0));
        float hn1 = fmaf(W.wn10, h0, fmaf(W.wn11, h1, W.bn1));
        float n0 = tanha(fmaf(tr0, 0.5f * hn0, fmaf(0.5f, hn0, ig[4])));
        float n1 = tanha(fmaf(tr1, 0.5f * hn1, fmaf(0.5f, hn1, ig[5])));
        float z0 = fmaf(0.5f, tz0, 0.5f), omz0 = fmaf(-0.5f, tz0, 0.5f);
        float z1 = fmaf(0.5f, tz1, 0.5f), omz1 = fmaf(-0.5f, tz1, 0.5f);
        float nh0 = fmaf(omz0, n0, z0 * h0);
        float nh1 = fmaf(omz1, n1, z1 * h1);
        h0 = nh0; h1 = nh1;
        hv[u] = h2bits(__floats2half2_rn(h0, h1));
    }
    if (store) {
        uint4* o4 = (uint4*)(hout + tb);
        o4[0] = make_uint4(hv[0], hv[1], hv[2], hv[3]);
        o4[1] = make_uint4(hv[4], hv[5], hv[6], hv[7]);
    }
}

__device__ __forceinline__ void fwd_load(float2 (&E)[8], int tg, int b)
{
#pragma unroll
    for (int u = 0; u < 8; u++) E[u] = g_E[(size_t)(tg + u) * BB + b];
}

__device__ __forceinline__ void fwd_body(float A00, float A01, float A10, float A11,
                                         float p0, float p1,
                                         const float2 (&E)[8],
                                         float& v0, float& v1,
                                         float2* __restrict__ vout, int tb,
                                         bool store, bool first)
{
    if (!first) { float iv = frcp(v0 + v1); v0 *= iv; v1 *= iv; }
#pragma unroll
    for (int u = 0; u < 8; u++) {
        float2 e = E[u];
        if (first && u == 0) {
            v0 = p0 * e.x; v1 = p1 * e.y;   // seg0: pi*E; warm start: E (p=1)
        } else {
            float u0 = fmaf(A00, v0, A10 * v1);
            float u1 = fmaf(A01, v0, A11 * v1);
            v0 = e.x * u0; v1 = e.y * u1;
        }
        if (store) vout[tb + u] = make_float2(v0, v1);
    }
}

__device__ __forceinline__ void bwd_load(float2 (&E)[8], int base, int b)
{
#pragma unroll
    for (int u = 0; u < 8; u++) E[u] = g_E[(size_t)(base - u) * BB + b];
}

__device__ __forceinline__ void bwd_body(float A00, float A01, float A10, float A11,
                                         const float2 (&E)[8],
                                         float& w0, float& w1,
                                         float2* __restrict__ vout, int ttop,
                                         bool store, bool first)
{
    if (!first) { float iv = frcp(w0 + w1); w0 *= iv; w1 *= iv; }
#pragma unroll
    for (int u = 0; u < 8; u++) {
        int t = ttop - u;
        float2 e = E[u];                  // = E[t+1] (pad row when t=T-1)
        if (first && u == 0) {
            w0 = 1.f; w1 = 1.f;
        } else {
            float u0 = e.x * w0, u1 = e.y * w1;
            float nw0 = fmaf(A00, u0, A01 * u1);
            float nw1 = fmaf(A10, u0, A11 * u1);
            w0 = nw0; w1 = nw1;
        }
        if (store) vout[t] = make_float2(w0, w1);
    }
}

// =====================================================================
// K2: segment-parallel scans (contraction warmup). 128 blocks x 128 thr.
//   gwarp [0,256)   : GRU (gates inline from x), 32 segments of 128 (+32 warmup)
//   gwarp [256,384) : HMM fwd, 16 segments of 256 (+32 warmup)
//   gwarp [384,512) : HMM bwd, 16 segments of 256 (+32 warmup)
// =====================================================================
__global__ __launch_bounds__(128) void k2_scan(
    const float* __restrict__ x,
    const float* __restrict__ w_ih, const float* __restrict__ b_ih,
    const float* __restrict__ w_hh, const float* __restrict__ b_hh,
    const float* __restrict__ log_pi, const float* __restrict__ log_A)
{
    int lane = threadIdx.x & 31;
    int gw   = blockIdx.x * 4 + (threadIdx.x >> 5);

    if (gw < 256) {
        // ---------------- GRU segment ----------------
        int bg = gw & 7, seg = gw >> 3;
        int b  = bg * 32 + lane;
        int t0 = seg * 128;
        int tstart = seg ? t0 - 32 : 0;        // warmup 32 (contraction ~0.6/step)
        int warm   = (t0 - tstart) >> 3;       // 0 or 4 groups
        int groups = warm + 16;

        GruW W;
        W.wr00 = 0.5f * __ldg(w_hh + 0);  W.wr01 = 0.5f * __ldg(w_hh + 1);
        W.wr10 = 0.5f * __ldg(w_hh + 2);  W.wr11 = 0.5f * __ldg(w_hh + 3);
        W.wz00 = 0.5f * __ldg(w_hh + 4);  W.wz01 = 0.5f * __ldg(w_hh + 5);
        W.wz10 = 0.5f * __ldg(w_hh + 6);  W.wz11 = 0.5f * __ldg(w_hh + 7);
        W.wn00 = __ldg(w_hh + 8);   W.wn01 = __ldg(w_hh + 9);
        W.wn10 = __ldg(w_hh + 10);  W.wn11 = __ldg(w_hh + 11);
        W.bn0  = __ldg(b_hh + 4);   W.bn1  = __ldg(b_hh + 5);
#pragma unroll
        for (int j = 0; j < 6; j++) {
            float s = (j < 4) ? 0.5f : 1.0f;
#pragma unroll
            for (int d = 0; d < 3; d++) W.wi[j][d] = s * __ldg(w_ih + j * 3 + d);
            W.bi[j] = (j < 4) ? 0.5f * (__ldg(b_ih + j) + __ldg(b_hh + j))
                              : __ldg(b_ih + j);
        }

        const float4* xp = (const float4*)(x + ((size_t)b * TT + tstart) * 3);
        float4 Xa[6], Xb[6];
        float h0 = 0.f, h1 = 0.f;
        unsigned* hout = g_h + (size_t)b * TT;

        x_load(Xa, xp, 0);
        for (int gi = 0; gi < groups; gi += 2) {
            x_load(Xb, xp, gi + 1);
            gru_body(W, Xa, h0, h1, hout, tstart + gi * 8, gi >= warm);
            if (gi + 2 < groups) x_load(Xa, xp, gi + 2);
            gru_body(W, Xb, h0, h1, hout, tstart + (gi + 1) * 8, gi + 1 >= warm);
        }
    } else {
        // shared transition matrix (row-softmax of log_A)
        float e00 = __expf(__ldg(log_A + 0)), e01 = __expf(__ldg(log_A + 1));
        float e10 = __expf(__ldg(log_A + 2)), e11 = __expf(__ldg(log_A + 3));
        float r0 = frcp(e00 + e01), r1 = frcp(e10 + e11);
        float A00 = e00 * r0, A01 = e01 * r0;
        float A10 = e10 * r1, A11 = e11 * r1;

        if (gw < 384) {
            // ---------------- forward segment ----------------
            int u = gw - 256;
            int bg = u & 7, seg = u >> 3;
            int b  = bg * 32 + lane;
            int t0 = seg * 256;
            int tstart = seg ? t0 - 32 : 0;
            int warm   = (t0 - tstart) >> 3;   // 0 or 4
            int groups = warm + 32;

            float p0 = 1.f, p1 = 1.f;
            if (seg == 0) {
                float q0 = __expf(__ldg(log_pi + 0)), q1 = __expf(__ldg(log_pi + 1));
                float rp = frcp(q0 + q1);
                p0 = q0 * rp; p1 = q1 * rp;
            }

            float2 Ea[8], Eb[8];
            float v0 = 0.f, v1 = 0.f;
            float2* vout = g_va + (size_t)b * TT;

            fwd_load(Ea, tstart, b);
            for (int gi = 0; gi < groups; gi += 2) {
                fwd_load(Eb, tstart + (gi + 1) * 8, b);
                fwd_body(A00, A01, A10, A11, p0, p1, Ea, v0, v1, vout,
                         tstart + gi * 8, gi >= warm, gi == 0);
                if (gi + 2 < groups) fwd_load(Ea, tstart + (gi + 2) * 8, b);
                fwd_body(A00, A01, A10, A11, p0, p1, Eb, v0, v1, vout,
                         tstart + (gi + 1) * 8, gi + 1 >= warm, false);
            }
        } else {
            // ---------------- backward segment ----------------
            int u = gw - 384;
            int bg = u & 7, seg = u >> 3;
            int b  = bg * 32 + lane;
            int t0 = seg * 256;
            bool last = (seg == 15);
            int tinit  = last ? (TT - 1) : (t0 + 255 + 32);
            int warm   = last ? 0 : 4;
            int groups = warm + 32;

            float2 Ea[8], Eb[8];
            float w0 = 1.f, w1 = 1.f;
            float2* vout = g_vb + (size_t)b * TT;

            bwd_load(Ea, tinit + 1, b);
            for (int gi = 0; gi < groups; gi += 2) {
                bwd_load(Eb, tinit + 1 - (gi + 1) * 8, b);
                bwd_body(A00, A01, A10, A11, Ea, w0, w1, vout,
                         tinit - gi * 8, gi >= warm, gi == 0);
                if (gi + 2 < groups) bwd_load(Ea, tinit + 1 - (gi + 2) * 8, b);
                bwd_body(A00, A01, A10, A11, Eb, w0, w1, vout,
                         tinit - (gi + 1) * 8, gi + 1 >= warm, false);
            }
        }
    }
}

// =====================================================================
// K3: parallel epilogue, 4 elements per thread, ALL accesses 128-bit.
// Streaming hints (__ldcs on Q, __stcs on out) protect scratch in L2.
// grid = (B*T)/(128*4) = 2048 blocks x 128 thr
// =====================================================================
__global__ __launch_bounds__(128) void k3_final(
    const float* __restrict__ Q,
    const float* __restrict__ Wg, const float* __restrict__ by,
    float* __restrict__ out)
{
    __shared__ float sW[20];
    __shared__ float sb[4];
    int tid = threadIdx.x;
    if (tid < 20) sW[tid] = Wg[tid];
    if (tid < 4)  sb[tid] = by[tid];
    __syncthreads();

    size_t qid = (size_t)blockIdx.x * 128 + tid;   // quad id; elems 4qid..4qid+3
    size_t g0  = qid * 4;

    float4 va[2], vb[2];
    va[0] = ((const float4*)g_va)[qid * 2];
    va[1] = ((const float4*)g_va)[qid * 2 + 1];
    vb[0] = ((const float4*)g_vb)[qid * 2];
    vb[1] = ((const float4*)g_vb)[qid * 2 + 1];
    uint4 hu4 = ((const uint4*)g_h)[qid];
    unsigned hu[4] = {hu4.x, hu4.y, hu4.z, hu4.w};

    const float4* qf = (const float4*)(Q + g0 * 10);
    float4 q4[10];
#pragma unroll
    for (int i = 0; i < 10; i++) q4[i] = __ldcs(qf + i);
    const float* q = (const float*)q4;             // 40 floats: elem e at [e*10 .. e*10+9]

    float pi_o[8], lg_o[8], gv[20];

#pragma unroll
    for (int e = 0; e < 4; e++) {
        float4 av = va[e >> 1], bv = vb[e >> 1];
        float a0 = (e & 1) ? av.z : av.x, a1 = (e & 1) ? av.w : av.y;
        float b0 = (e & 1) ? bv.z : bv.x, b1 = (e & 1) ? bv.w : bv.y;
        float2 h = __half22float2(bits2h(hu[e]));

        float p0 = a0 * b0, p1 = a1 * b1;
        float inv = frcp(p0 + p1);
        float gm0 = p0 * inv, gm1 = p1 * inv;
        lg_o[e * 2 + 0] = __logf(gm0);
        lg_o[e * 2 + 1] = __logf(gm1);

        float s0 = 0.f, s1 = 0.f;
        float E0[5], E1[5];
#pragma unroll
        for (int j = 0; j < 5; j++) {
            E0[j] = __expf(fmaf(h.x, sW[j],      h.y * sW[5 + j]));
            E1[j] = __expf(fmaf(h.x, sW[10 + j], h.y * sW[15 + j]));
            s0 += E0[j]; s1 += E1[j];
        }
        float c0 = gm0 * frcp(s0), c1 = gm1 * frcp(s1);

        float V0 = fmaf(gm0, sb[0], gm1 * sb[2]);
        float V1 = fmaf(gm0, sb[1], gm1 * sb[3]);
#pragma unroll
        for (int j = 0; j < 5; j++) {
            float ga = fmaf(c0, E0[j], c1 * E1[j]);
            gv[e * 5 + j] = ga;
            V0 = fmaf(ga, q[e * 10 + j * 2 + 0], V0);
            V1 = fmaf(ga, q[e * 10 + j * 2 + 1], V1);
        }
        float mx = fmaxf(V0, V1), mn = fminf(V0, V1);
        float lse = mx + __logf(1.f + __expf(mn - mx));
        pi_o[e * 2 + 0] = V0 - lse;
        pi_o[e * 2 + 1] = V1 - lse;
    }

    const size_t N = (size_t)BB * TT;
    float4* po = (float4*)out + qid * 2;                       // pi_log [B,T,2]
    __stcs(po + 0, make_float4(pi_o[0], pi_o[1], pi_o[2], pi_o[3]));
    __stcs(po + 1, make_float4(pi_o[4], pi_o[5], pi_o[6], pi_o[7]));
    float4* gp = (float4*)(out + N * 2) + qid * 5;             // g [B,T,5]
#pragma unroll
    for (int i = 0; i < 5; i++)
        __stcs(gp + i, make_float4(gv[i * 4 + 0], gv[i * 4 + 1],
                                   gv[i * 4 + 2], gv[i * 4 + 3]));
    float4* lp = (float4*)(out + N * 7) + qid * 2;             // log_gamma [B,T,2]
    __stcs(lp + 0, make_float4(lg_o[0], lg_o[1], lg_o[2], lg_o[3]));
    __stcs(lp + 1, make_float4(lg_o[4], lg_o[5], lg_o[6], lg_o[7]));
}

// =====================================================================
extern "C" void kernel_launch(void* const* d_in, const int* in_sizes, int n_in,
                              void* d_out, int out_size) {
    const float* x      = (const float*)d_in[0];
    const float* Q_seq  = (const float*)d_in[1];
    const float* log_pi = (const float*)d_in[2];
    const float* log_A  = (const float*)d_in[3];
    const float* fc1_w  = (const float*)d_in[4];
    const float* fc1_b  = (const float*)d_in[5];
    const float* fc2_w  = (const float*)d_in[6];
    const float* fc2_b  = (const float*)d_in[7];
    const float* w_ih   = (const float*)d_in[8];
    const float* w_hh   = (const float*)d_in[9];
    const float* b_ih   = (const float*)d_in[10];
    const float* b_hh   = (const float*)d_in[11];
    const float* Wg     = (const float*)d_in[12];
    const float* by     = (const float*)d_in[13];
    float* out = (float*)d_out;

    k1_emit<<<512, 128>>>(x, fc1_w, fc1_b, fc2_w, fc2_b);
    k2_scan<<<128, 128>>>(x, w_ih, b_ih, w_hh, b_hh, log_pi, log_A);
    k3_final<<<(BB * TT) / 512, 128>>>(Q_seq, Wg, by, out);
}